// round 8
// baseline (speedup 1.0000x reference)
#include <cuda_runtime.h>

// TripletLoss:  loss = mean_b[ (1/D)(||a_t||^2 - ||a_n||^2 + 2(pred_b·a_n - pred_b·a_t)) + MARGIN ]
// pred [16384,4096] f32, anchors [10,4096] f32, clss [16384] int, neg_offset [16384] int.
// HBM-bound: single 256 MB streaming read of pred. Anchors staged in smem (164 KB).

#define NB      16384
#define ND      4096
#define NC      10
#define NV      (ND / 4)        // float4 per row = 1024
#define THREADS 512
#define WARPS   (THREADS / 32)  // 16
#define GRID    152             // GB300 SM count
#define MARGIN  0.1f

__device__ int g_idx_is64;

// Detect whether the index tensors are int64 or int32.
// If int64 (little-endian), every odd 32-bit word (high half) is 0 and every
// even word is a value in [0,10). If int32, the odd words are themselves class
// values 0..9 — the chance all 32 of them are zero is 1e-32.
__global__ void detect_dtype_kernel(const unsigned int* __restrict__ raw) {
    if (threadIdx.x == 0) {
        int is64 = 1;
        #pragma unroll
        for (int i = 0; i < 32; i++) {
            unsigned lo = raw[2 * i];
            unsigned hi = raw[2 * i + 1];
            if (hi != 0u || lo >= 10u) is64 = 0;
        }
        g_idx_is64 = is64;
    }
}

__global__ __launch_bounds__(THREADS, 1)
void triplet_loss_kernel(const float4* __restrict__ pred4,
                         const float4* __restrict__ anch4,
                         const void*   __restrict__ clss_p,
                         const void*   __restrict__ off_p,
                         float*        __restrict__ out)
{
    extern __shared__ float smem[];
    float4* s_anch = reinterpret_cast<float4*>(smem);   // [NC * NV] float4
    float*  s_norm = smem + NC * ND;                    // [NC] (padded region)
    float*  s_part = s_norm + 16;                       // [WARPS]

    const int tid  = threadIdx.x;
    const int wid  = tid >> 5;
    const int lane = tid & 31;

    // ---- Stage all anchors into shared memory (160 KB) ----
    for (int i = tid; i < NC * NV; i += THREADS)
        s_anch[i] = anch4[i];
    __syncthreads();

    // ---- Anchor squared norms (warp w handles class w) ----
    if (wid < NC) {
        const float4* row = s_anch + wid * NV;
        float s = 0.f;
        for (int k = lane; k < NV; k += 32) {
            float4 v = row[k];
            s = fmaf(v.x, v.x, s); s = fmaf(v.y, v.y, s);
            s = fmaf(v.z, v.z, s); s = fmaf(v.w, v.w, s);
        }
        #pragma unroll
        for (int o = 16; o > 0; o >>= 1) s += __shfl_xor_sync(0xffffffffu, s, o);
        if (lane == 0) s_norm[wid] = s;
    }
    __syncthreads();

    const int is64 = g_idx_is64;
    const long long* cl64 = (const long long*)clss_p;
    const int*       cl32 = (const int*)clss_p;
    const long long* of64 = (const long long*)off_p;
    const int*       of32 = (const int*)off_p;

    // ---- One warp per row, grid-stride over rows ----
    float wsum = 0.f;
    const int gw     = blockIdx.x * WARPS + wid;
    const int nwarps = gridDim.x * WARPS;

    for (int b = gw; b < NB; b += nwarps) {
        long long t, o;
        if (is64) { t = cl64[b]; o = of64[b]; }
        else      { t = (long long)cl32[b]; o = (long long)of32[b]; }
        const int ti = (int)t;
        const int ni = (int)((t + 1 + (o % 9)) % 10);

        const float4* p  = pred4 + (size_t)b * NV;
        const float4* at = s_anch + ti * NV;
        const float4* an = s_anch + ni * NV;

        float dt = 0.f, dn = 0.f;
        #pragma unroll 8
        for (int k = lane; k < NV; k += 32) {
            const float4 pv = __ldcs(p + k);   // streaming: no reuse of pred
            const float4 av = at[k];
            const float4 nv = an[k];
            dt = fmaf(pv.x, av.x, dt); dt = fmaf(pv.y, av.y, dt);
            dt = fmaf(pv.z, av.z, dt); dt = fmaf(pv.w, av.w, dt);
            dn = fmaf(pv.x, nv.x, dn); dn = fmaf(pv.y, nv.y, dn);
            dn = fmaf(pv.z, nv.z, dn); dn = fmaf(pv.w, nv.w, dn);
        }
        float diff = dn - dt;
        #pragma unroll
        for (int o2 = 16; o2 > 0; o2 >>= 1)
            diff += __shfl_xor_sync(0xffffffffu, diff, o2);

        if (lane == 0) {
            // mse_pos - mse_neg + MARGIN
            wsum += (2.f * diff + s_norm[ti] - s_norm[ni]) * (1.f / (float)ND) + MARGIN;
        }
    }

    // ---- Block reduction, one atomic per block ----
    if (lane == 0) s_part[wid] = wsum;
    __syncthreads();
    if (wid == 0) {
        float v = (lane < WARPS) ? s_part[lane] : 0.f;
        #pragma unroll
        for (int o = 16; o > 0; o >>= 1) v += __shfl_xor_sync(0xffffffffu, v, o);
        if (lane == 0) atomicAdd(out, v * (1.f / (float)NB));
    }
}

extern "C" void kernel_launch(void* const* d_in, const int* in_sizes, int n_in,
                              void* d_out, int out_size) {
    const float4* pred = (const float4*)d_in[0];
    const float4* anch = (const float4*)d_in[1];
    const void*   clss = d_in[2];
    const void*   noff = d_in[3];
    float*        out  = (float*)d_out;

    const size_t smem_bytes = (size_t)(NC * ND + 16 + WARPS) * sizeof(float); // ~164 KB
    // Idempotent, not a stream op — safe to call on every invocation (incl. capture).
    cudaFuncSetAttribute(triplet_loss_kernel,
                         cudaFuncAttributeMaxDynamicSharedMemorySize, (int)smem_bytes);

    cudaMemsetAsync(d_out, 0, (size_t)out_size * sizeof(float));
    detect_dtype_kernel<<<1, 32>>>((const unsigned int*)clss);
    triplet_loss_kernel<<<GRID, THREADS, smem_bytes>>>(pred, anch, clss, noff, out);
}

// round 10
// speedup vs baseline: 1.0465x; 1.0465x over previous
#include <cuda_runtime.h>

// TripletLoss:  loss = mean_b[ (1/D)(||a_t||^2 - ||a_n||^2 + 2(pred_b·a_n - pred_b·a_t)) + MARGIN ]
// pred [16384,4096] f32, anchors [10,4096] f32, clss [16384] int32/64, neg_offset [16384] int32/64.
// HBM-bound: one 256 MB streaming read of pred (~37 us floor at ~7 TB/s achieved).
// R8 was 51.2us at occ=24.4%, dram=64% -> latency-limited. This round: 1024 thr/block
// (32 warps/SM), half-row work items for tail balance, inlined dtype detection.

#define NB      16384
#define ND      4096
#define NC      10
#define NV      (ND / 4)        // float4 per row = 1024
#define NHALF   (NV / 2)        // float4 per half-row = 512
#define THREADS 1024
#define WARPS   (THREADS / 32)  // 32
#define GRID    152             // GB300 SM count
#define MARGIN  0.1f

__global__ __launch_bounds__(THREADS, 1)
void triplet_loss_kernel(const float4* __restrict__ pred4,
                         const float4* __restrict__ anch4,
                         const void*   __restrict__ clss_p,
                         const void*   __restrict__ off_p,
                         float*        __restrict__ out)
{
    extern __shared__ float smem[];
    float4* s_anch = reinterpret_cast<float4*>(smem);   // [NC * NV] float4 (160 KB)
    float*  s_norm = smem + NC * ND;                    // [16]
    float*  s_part = s_norm + 16;                       // [WARPS]
    int*    s_is64 = (int*)(s_part + WARPS);            // [1]

    const int tid  = threadIdx.x;
    const int wid  = tid >> 5;
    const int lane = tid & 31;

    // ---- Dtype detection (thread 0) overlapped with anchor staging ----
    // int64 little-endian: every odd 32-bit word is 0 and every even word < 10.
    // For int32 data the odd words are class values; P(all 32 zero) ~ 1e-32.
    if (tid == 0) {
        const unsigned* raw = (const unsigned*)clss_p;
        int is64 = 1;
        #pragma unroll
        for (int i = 0; i < 32; i++) {
            if (raw[2 * i + 1] != 0u || raw[2 * i] >= 10u) is64 = 0;
        }
        *s_is64 = is64;
    }

    // ---- Stage all anchors into shared memory ----
    for (int i = tid; i < NC * NV; i += THREADS)
        s_anch[i] = anch4[i];
    __syncthreads();

    // ---- Anchor squared norms (warp w handles class w) ----
    if (wid < NC) {
        const float4* row = s_anch + wid * NV;
        float s = 0.f;
        for (int k = lane; k < NV; k += 32) {
            float4 v = row[k];
            s = fmaf(v.x, v.x, s); s = fmaf(v.y, v.y, s);
            s = fmaf(v.z, v.z, s); s = fmaf(v.w, v.w, s);
        }
        #pragma unroll
        for (int o = 16; o > 0; o >>= 1) s += __shfl_xor_sync(0xffffffffu, s, o);
        if (lane == 0) s_norm[wid] = s;
    }
    __syncthreads();

    const int is64 = *s_is64;
    const long long* cl64 = (const long long*)clss_p;
    const int*       cl32 = (const int*)clss_p;
    const long long* of64 = (const long long*)off_p;
    const int*       of32 = (const int*)off_p;

    // ---- Work item = half row. 32768 items over 4864 warps -> 96% balanced ----
    float wsum = 0.f;
    const int gw      = blockIdx.x * WARPS + wid;
    const int nwarps  = GRID * WARPS;
    const int n_items = 2 * NB;

    for (int item = gw; item < n_items; item += nwarps) {
        const int b = item >> 1;
        const int h = item & 1;

        long long t, o;
        if (is64) { t = cl64[b]; o = of64[b]; }
        else      { t = (long long)cl32[b]; o = (long long)of32[b]; }
        const int ti = (int)t;
        const int ni = (int)((t + 1 + (o % 9)) % 10);

        const float4* p  = pred4 + (size_t)b * NV + h * NHALF;
        const float4* at = s_anch + ti * NV + h * NHALF;
        const float4* an = s_anch + ni * NV + h * NHALF;

        float dt = 0.f, dn = 0.f;
        #pragma unroll 4
        for (int k = lane; k < NHALF; k += 32) {
            const float4 pv = __ldcs(p + k);   // streaming: pred has no reuse
            const float4 av = at[k];
            const float4 nv = an[k];
            dt = fmaf(pv.x, av.x, dt); dt = fmaf(pv.y, av.y, dt);
            dt = fmaf(pv.z, av.z, dt); dt = fmaf(pv.w, av.w, dt);
            dn = fmaf(pv.x, nv.x, dn); dn = fmaf(pv.y, nv.y, dn);
            dn = fmaf(pv.z, nv.z, dn); dn = fmaf(pv.w, nv.w, dn);
        }
        float diff = dn - dt;
        #pragma unroll
        for (int o2 = 16; o2 > 0; o2 >>= 1)
            diff += __shfl_xor_sync(0xffffffffu, diff, o2);

        if (lane == 0) {
            // 2*(pred.an - pred.at)/D for this half; norm+margin terms once per row.
            float contrib = 2.f * diff * (1.f / (float)ND);
            if (h == 0)
                contrib += (s_norm[ti] - s_norm[ni]) * (1.f / (float)ND) + MARGIN;
            wsum += contrib;
        }
    }

    // ---- Block reduction, one atomic per block ----
    if (lane == 0) s_part[wid] = wsum;
    __syncthreads();
    if (wid == 0) {
        float v = (lane < WARPS) ? s_part[lane] : 0.f;
        #pragma unroll
        for (int o = 16; o > 0; o >>= 1) v += __shfl_xor_sync(0xffffffffu, v, o);
        if (lane == 0) atomicAdd(out, v * (1.f / (float)NB));
    }
}

extern "C" void kernel_launch(void* const* d_in, const int* in_sizes, int n_in,
                              void* d_out, int out_size) {
    const float4* pred = (const float4*)d_in[0];
    const float4* anch = (const float4*)d_in[1];
    const void*   clss = d_in[2];
    const void*   noff = d_in[3];
    float*        out  = (float*)d_out;

    const size_t smem_bytes = (size_t)(NC * ND + 16 + WARPS + 1) * sizeof(float); // ~164 KB
    // Idempotent attribute set — safe under graph capture.
    cudaFuncSetAttribute(triplet_loss_kernel,
                         cudaFuncAttributeMaxDynamicSharedMemorySize, (int)smem_bytes);

    cudaMemsetAsync(d_out, 0, (size_t)out_size * sizeof(float));
    triplet_loss_kernel<<<GRID, THREADS, smem_bytes>>>(pred, anch, clss, noff, out);
}